// round 1
// baseline (speedup 1.0000x reference)
#include <cuda_runtime.h>
#include <cstdint>

// Problem constants (fixed-shape problem)
#define T_TOK  8192
#define NHEAD  16
#define HKV    4
#define GQA    4          // NHEAD / HKV
#define HDIM   128
#define NBLK   64
#define BLKSZ  256
#define BATCH  4
#define BPS    8
#define SEQ    2048       // BPS * BLKSZ
#define SCALE  0.08838834764831845f
#define LOG2E  1.4426950408889634f

#define BM 128
#define BN 64
#define QSTRIDE 132       // 128 + 4 pad  (bank-conflict-free A frags)
#define KSTRIDE 132       // 128 + 4 pad  (bank-conflict-free QK B frags)
#define VSTRIDE 136       // 128 + 8 pad  (bank-conflict-free PV B frags)
#define PSTRIDE 68        // 64 + 4 pad

#define SMEM_FLOATS (BM*QSTRIDE + BN*KSTRIDE + BN*VSTRIDE + BM*PSTRIDE)
#define SMEM_BYTES  (SMEM_FLOATS * 4)

// Scratch paged caches (device globals: no allocation in kernel_launch)
__device__ float g_kc[(size_t)NBLK * BLKSZ * HKV * HDIM];
__device__ float g_vc[(size_t)NBLK * BLKSZ * HKV * HDIM];

__device__ __forceinline__ uint32_t f2tf(float x) {
    uint32_t r;
    asm("cvt.rna.tf32.f32 %0, %1;" : "=r"(r) : "f"(x));
    return r;
}
__device__ __forceinline__ float ex2f(float x) {
    float r;
    asm("ex2.approx.f32 %0, %1;" : "=f"(r) : "f"(x));
    return r;
}
__device__ __forceinline__ void mma_tf32(float c[4], const uint32_t a[4], const uint32_t b[2]) {
    asm volatile(
        "mma.sync.aligned.m16n8k8.row.col.f32.tf32.tf32.f32 "
        "{%0,%1,%2,%3}, {%4,%5,%6,%7}, {%8,%9}, {%0,%1,%2,%3};"
        : "+f"(c[0]), "+f"(c[1]), "+f"(c[2]), "+f"(c[3])
        : "r"(a[0]), "r"(a[1]), "r"(a[2]), "r"(a[3]), "r"(b[0]), "r"(b[1]));
}

// ---------------- KV cache scatter ----------------
__global__ void scatter_kv(const float* __restrict__ k, const float* __restrict__ v,
                           const int* __restrict__ slot_mapping) {
    int g = blockIdx.x * blockDim.x + threadIdx.x;  // float4 index: token*(512/4)
    int t   = g >> 7;
    int rem = g & 127;
    if (t >= T_TOK) return;
    int slot = slot_mapping[t];
    if (slot < 0) return;
    const float4* ks = (const float4*)k;
    const float4* vs = (const float4*)v;
    float4* kd = (float4*)g_kc;
    float4* vd = (float4*)g_vc;
    kd[(size_t)slot * 128 + rem] = ks[(size_t)t * 128 + rem];
    vd[(size_t)slot * 128 + rem] = vs[(size_t)t * 128 + rem];
}

// ---------------- Flash attention (tf32 mma.sync) ----------------
__global__ void __launch_bounds__(256, 1)
attn_kernel(const float* __restrict__ q, const int* __restrict__ bt,
            float* __restrict__ out) {
    const int qi = blockIdx.x;   // q tile (0..15)
    const int h  = blockIdx.y;   // head
    const int b  = blockIdx.z;   // batch
    const int kvh = h / GQA;

    extern __shared__ float smem[];
    float* sQ = smem;                       // [BM][QSTRIDE]
    float* sK = sQ + BM * QSTRIDE;          // [BN][KSTRIDE]
    float* sV = sK + BN * KSTRIDE;          // [BN][VSTRIDE]
    float* sP = sV + BN * VSTRIDE;          // [BM][PSTRIDE]

    const int tid  = threadIdx.x;
    const int lane = tid & 31;
    const int warp = tid >> 5;
    const int gID  = lane >> 2;
    const int tig  = lane & 3;

    // Load Q tile (tf32-rounded)
    {
        int row  = tid >> 1;
        int half = tid & 1;
        const float4* src = (const float4*)(q +
            (((size_t)(b * SEQ + qi * BM + row)) * NHEAD + h) * HDIM + half * 64);
        float* dst = sQ + row * QSTRIDE + half * 64;
        #pragma unroll
        for (int j = 0; j < 16; j++) {
            float4 v4 = src[j];
            uint32_t* d = (uint32_t*)(dst + j * 4);
            d[0] = f2tf(v4.x); d[1] = f2tf(v4.y); d[2] = f2tf(v4.z); d[3] = f2tf(v4.w);
        }
    }

    float o[16][4];
    #pragma unroll
    for (int nt = 0; nt < 16; nt++) { o[nt][0]=o[nt][1]=o[nt][2]=o[nt][3]=0.f; }
    float m0 = -1e30f, m1 = -1e30f, l0 = 0.f, l1 = 0.f;

    const int nkt   = 2 * qi + 2;
    const int rowg0 = qi * BM + warp * 16 + gID;
    const int rowg1 = rowg0 + 8;
    const float kf  = SCALE * LOG2E;

    const uint32_t* Qb = (const uint32_t*)sQ;
    const uint32_t* Kb = (const uint32_t*)sK;
    const uint32_t* Vb = (const uint32_t*)sV;
    const uint32_t* Pb = (const uint32_t*)sP;

    for (int kt = 0; kt < nkt; kt++) {
        __syncthreads();  // prior PV reads of sK/sV done
        // Load K,V tile via paged gather (tf32-rounded)
        {
            int row = tid >> 2;
            int qtr = tid & 3;
            int s = kt * BN + row;
            int blk = bt[b * BPS + (s >> 8)];
            size_t slot = (size_t)blk * BLKSZ + (s & 255);
            const float4* ksrc = (const float4*)(g_kc + (slot * HKV + kvh) * HDIM + qtr * 32);
            const float4* vsrc = (const float4*)(g_vc + (slot * HKV + kvh) * HDIM + qtr * 32);
            float* kdst = sK + row * KSTRIDE + qtr * 32;
            float* vdst = sV + row * VSTRIDE + qtr * 32;
            #pragma unroll
            for (int j = 0; j < 8; j++) {
                float4 kv4 = ksrc[j];
                uint32_t* kd = (uint32_t*)(kdst + j * 4);
                kd[0]=f2tf(kv4.x); kd[1]=f2tf(kv4.y); kd[2]=f2tf(kv4.z); kd[3]=f2tf(kv4.w);
                float4 vv4 = vsrc[j];
                uint32_t* vd = (uint32_t*)(vdst + j * 4);
                vd[0]=f2tf(vv4.x); vd[1]=f2tf(vv4.y); vd[2]=f2tf(vv4.z); vd[3]=f2tf(vv4.w);
            }
        }
        __syncthreads();

        // S = Q K^T  (warp: rows warp*16..+15, cols 0..63)
        float sacc[8][4];
        #pragma unroll
        for (int nt = 0; nt < 8; nt++) { sacc[nt][0]=sacc[nt][1]=sacc[nt][2]=sacc[nt][3]=0.f; }
        const int arow = warp * 16 + gID;
        #pragma unroll
        for (int ks = 0; ks < 16; ks++) {
            uint32_t a[4];
            a[0] = Qb[ arow      * QSTRIDE + ks * 8 + tig    ];
            a[1] = Qb[(arow + 8) * QSTRIDE + ks * 8 + tig    ];
            a[2] = Qb[ arow      * QSTRIDE + ks * 8 + tig + 4];
            a[3] = Qb[(arow + 8) * QSTRIDE + ks * 8 + tig + 4];
            #pragma unroll
            for (int nt = 0; nt < 8; nt++) {
                uint32_t bb[2];
                bb[0] = Kb[(nt * 8 + gID) * KSTRIDE + ks * 8 + tig    ];
                bb[1] = Kb[(nt * 8 + gID) * KSTRIDE + ks * 8 + tig + 4];
                mma_tf32(sacc[nt], a, bb);
            }
        }

        // Causal mask (only last two K tiles intersect the diagonal)
        if (kt >= 2 * qi) {
            #pragma unroll
            for (int nt = 0; nt < 8; nt++) {
                int colg = kt * BN + nt * 8 + 2 * tig;
                if (colg     > rowg0) sacc[nt][0] = -1e30f;
                if (colg + 1 > rowg0) sacc[nt][1] = -1e30f;
                if (colg     > rowg1) sacc[nt][2] = -1e30f;
                if (colg + 1 > rowg1) sacc[nt][3] = -1e30f;
            }
        }

        // Online softmax: row max (4-lane groups share a row)
        float mx0 = -1e30f, mx1 = -1e30f;
        #pragma unroll
        for (int nt = 0; nt < 8; nt++) {
            mx0 = fmaxf(mx0, fmaxf(sacc[nt][0], sacc[nt][1]));
            mx1 = fmaxf(mx1, fmaxf(sacc[nt][2], sacc[nt][3]));
        }
        mx0 = fmaxf(mx0, __shfl_xor_sync(0xffffffffu, mx0, 1));
        mx0 = fmaxf(mx0, __shfl_xor_sync(0xffffffffu, mx0, 2));
        mx1 = fmaxf(mx1, __shfl_xor_sync(0xffffffffu, mx1, 1));
        mx1 = fmaxf(mx1, __shfl_xor_sync(0xffffffffu, mx1, 2));
        float mn0 = fmaxf(m0, mx0);
        float mn1 = fmaxf(m1, mx1);
        float r0 = ex2f((m0 - mn0) * kf);
        float r1 = ex2f((m1 - mn1) * kf);
        m0 = mn0; m1 = mn1;
        l0 *= r0;  l1 *= r1;
        #pragma unroll
        for (int nt = 0; nt < 16; nt++) {
            o[nt][0] *= r0; o[nt][1] *= r0; o[nt][2] *= r1; o[nt][3] *= r1;
        }

        // exp, P -> smem (tf32), row sums
        float rs0 = 0.f, rs1 = 0.f;
        {
            const int prow = warp * 16 + gID;
            #pragma unroll
            for (int nt = 0; nt < 8; nt++) {
                float p0 = ex2f((sacc[nt][0] - m0) * kf);
                float p1 = ex2f((sacc[nt][1] - m0) * kf);
                float p2 = ex2f((sacc[nt][2] - m1) * kf);
                float p3 = ex2f((sacc[nt][3] - m1) * kf);
                rs0 += p0 + p1;  rs1 += p2 + p3;
                uint32_t* pp = (uint32_t*)(sP +  prow      * PSTRIDE + nt * 8 + 2 * tig);
                pp[0] = f2tf(p0); pp[1] = f2tf(p1);
                uint32_t* pq = (uint32_t*)(sP + (prow + 8) * PSTRIDE + nt * 8 + 2 * tig);
                pq[0] = f2tf(p2); pq[1] = f2tf(p3);
            }
        }
        rs0 += __shfl_xor_sync(0xffffffffu, rs0, 1);
        rs0 += __shfl_xor_sync(0xffffffffu, rs0, 2);
        rs1 += __shfl_xor_sync(0xffffffffu, rs1, 1);
        rs1 += __shfl_xor_sync(0xffffffffu, rs1, 2);
        l0 += rs0;  l1 += rs1;

        __syncwarp();  // P visible within warp (P rows are warp-private)

        // O += P V
        const int prow = warp * 16 + gID;
        #pragma unroll
        for (int ks = 0; ks < 8; ks++) {
            uint32_t a[4];
            a[0] = Pb[ prow      * PSTRIDE + ks * 8 + tig    ];
            a[1] = Pb[(prow + 8) * PSTRIDE + ks * 8 + tig    ];
            a[2] = Pb[ prow      * PSTRIDE + ks * 8 + tig + 4];
            a[3] = Pb[(prow + 8) * PSTRIDE + ks * 8 + tig + 4];
            #pragma unroll
            for (int nt = 0; nt < 16; nt++) {
                uint32_t bb[2];
                bb[0] = Vb[(ks * 8 + tig    ) * VSTRIDE + nt * 8 + gID];
                bb[1] = Vb[(ks * 8 + tig + 4) * VSTRIDE + nt * 8 + gID];
                mma_tf32(o[nt], a, bb);
            }
        }
    }

    // Epilogue: normalize and store (4-lane groups cover full 32B sectors)
    float inv0 = 1.f / l0;
    float inv1 = 1.f / l1;
    float* out0 = out + (((size_t)b * SEQ + rowg0) * NHEAD + h) * HDIM;
    float* out1 = out + (((size_t)b * SEQ + rowg1) * NHEAD + h) * HDIM;
    #pragma unroll
    for (int nt = 0; nt < 16; nt++) {
        float2 v0 = make_float2(o[nt][0] * inv0, o[nt][1] * inv0);
        float2 v1 = make_float2(o[nt][2] * inv1, o[nt][3] * inv1);
        *(float2*)(out0 + nt * 8 + 2 * tig) = v0;
        *(float2*)(out1 + nt * 8 + 2 * tig) = v1;
    }
}

extern "C" void kernel_launch(void* const* d_in, const int* in_sizes, int n_in,
                              void* d_out, int out_size) {
    (void)in_sizes; (void)n_in; (void)out_size;
    const float* q  = (const float*)d_in[0];
    const float* k  = (const float*)d_in[1];
    const float* v  = (const float*)d_in[2];
    // d_in[3], d_in[4]: k_cache/v_cache inputs (zeros) — we scatter into device-global scratch instead
    const int* slot_mapping = (const int*)d_in[5];
    const int* block_tables = (const int*)d_in[6];
    float* out = (float*)d_out;

    cudaFuncSetAttribute(attn_kernel, cudaFuncAttributeMaxDynamicSharedMemorySize, SMEM_BYTES);

    // 1) paged KV store
    int n4 = T_TOK * 128;  // float4 elements per tensor
    scatter_kv<<<(n4 + 255) / 256, 256>>>(k, v, slot_mapping);

    // 2) causal GQA flash attention through the paged cache
    dim3 grid(SEQ / BM, NHEAD, BATCH);
    attn_kernel<<<grid, 256, SMEM_BYTES>>>(q, block_tables, out);
}

// round 2
// speedup vs baseline: 1.6646x; 1.6646x over previous
#include <cuda_runtime.h>
#include <cuda_fp16.h>
#include <cstdint>

// Problem constants (fixed-shape problem)
#define T_TOK  8192
#define NHEAD  16
#define HKV    4
#define GQA    4
#define HDIM   128
#define NBLK   64
#define BLKSZ  256
#define BATCH  4
#define BPS    8
#define SEQ    2048
#define SCALE  0.08838834764831845f
#define LOG2E  1.4426950408889634f

#define BM 128
#define BN 64
#define QS 136   // half stride: 272B = 17*16B -> conflict-free ldmatrix
#define KS 136
#define VS 136

#define SMEM_BYTES ((BM*QS + BN*KS + BN*VS) * 2)   // 69632 B -> 2 CTAs/SM

__device__ float g_kc[(size_t)NBLK * BLKSZ * HKV * HDIM];
__device__ float g_vc[(size_t)NBLK * BLKSZ * HKV * HDIM];

__device__ __forceinline__ float ex2f(float x) {
    float r; asm("ex2.approx.f32 %0, %1;" : "=f"(r) : "f"(x)); return r;
}
__device__ __forceinline__ uint32_t packh2(float lo, float hi) {
    __half2 h = __floats2half2_rn(lo, hi);
    return *reinterpret_cast<uint32_t*>(&h);
}
__device__ __forceinline__ uint32_t cvta_s(const void* p) {
    return (uint32_t)__cvta_generic_to_shared(p);
}
__device__ __forceinline__ void ldsm4(uint32_t& r0, uint32_t& r1, uint32_t& r2, uint32_t& r3, uint32_t addr) {
    asm volatile("ldmatrix.sync.aligned.m8n8.x4.shared.b16 {%0,%1,%2,%3}, [%4];"
                 : "=r"(r0), "=r"(r1), "=r"(r2), "=r"(r3) : "r"(addr));
}
__device__ __forceinline__ void ldsm4t(uint32_t& r0, uint32_t& r1, uint32_t& r2, uint32_t& r3, uint32_t addr) {
    asm volatile("ldmatrix.sync.aligned.m8n8.x4.trans.shared.b16 {%0,%1,%2,%3}, [%4];"
                 : "=r"(r0), "=r"(r1), "=r"(r2), "=r"(r3) : "r"(addr));
}
__device__ __forceinline__ void mma16816(float c[4], uint32_t a0, uint32_t a1, uint32_t a2, uint32_t a3,
                                         uint32_t b0, uint32_t b1) {
    asm volatile(
        "mma.sync.aligned.m16n8k16.row.col.f32.f16.f16.f32 "
        "{%0,%1,%2,%3}, {%4,%5,%6,%7}, {%8,%9}, {%0,%1,%2,%3};"
        : "+f"(c[0]), "+f"(c[1]), "+f"(c[2]), "+f"(c[3])
        : "r"(a0), "r"(a1), "r"(a2), "r"(a3), "r"(b0), "r"(b1));
}

// ---------------- KV cache scatter ----------------
__global__ void scatter_kv(const float* __restrict__ k, const float* __restrict__ v,
                           const int* __restrict__ slot_mapping) {
    int g = blockIdx.x * blockDim.x + threadIdx.x;
    int t   = g >> 7;
    int rem = g & 127;
    if (t >= T_TOK) return;
    int slot = slot_mapping[t];
    if (slot < 0) return;
    const float4* ks = (const float4*)k;
    const float4* vs = (const float4*)v;
    float4* kd = (float4*)g_kc;
    float4* vd = (float4*)g_vc;
    kd[(size_t)slot * 128 + rem] = ks[(size_t)t * 128 + rem];
    vd[(size_t)slot * 128 + rem] = vs[(size_t)t * 128 + rem];
}

// ---------------- Flash attention (fp16 mma + ldmatrix, P in regs) ----------------
__global__ void __launch_bounds__(256, 2)
attn_kernel(const float* __restrict__ q, const int* __restrict__ bt,
            float* __restrict__ out) {
    const int qi = blockIdx.x;
    const int h  = blockIdx.y;
    const int b  = blockIdx.z;
    const int kvh = h / GQA;

    extern __shared__ __half smem_h[];
    __half* sQ = smem_h;              // [BM][QS]
    __half* sK = sQ + BM * QS;        // [BN][KS]
    __half* sV = sK + BN * KS;        // [BN][VS]

    const int tid  = threadIdx.x;
    const int lane = tid & 31;
    const int warp = tid >> 5;
    const int gID  = lane >> 2;
    const int tig  = lane & 3;

    // ---- Load Q tile -> fp16 smem ----
    {
        int row  = tid >> 1;
        int hs   = tid & 1;
        const float4* src = (const float4*)(q +
            (((size_t)(b * SEQ + qi * BM + row)) * NHEAD + h) * HDIM + hs * 64);
        uint4* dst = (uint4*)(sQ + row * QS + hs * 64);
        #pragma unroll
        for (int j = 0; j < 8; j++) {
            float4 u = src[2*j], w = src[2*j+1];
            uint4 t4;
            t4.x = packh2(u.x, u.y); t4.y = packh2(u.z, u.w);
            t4.z = packh2(w.x, w.y); t4.w = packh2(w.z, w.w);
            dst[j] = t4;
        }
    }

    float o[16][4];
    #pragma unroll
    for (int nt = 0; nt < 16; nt++) { o[nt][0]=o[nt][1]=o[nt][2]=o[nt][3]=0.f; }
    float m0 = -1e30f, m1 = -1e30f, l0 = 0.f, l1 = 0.f;

    const int nkt   = 2 * qi + 2;
    const int rowg0 = qi * BM + warp * 16 + gID;
    const int rowg1 = rowg0 + 8;
    const float kf  = SCALE * LOG2E;

    // ldmatrix per-thread base addresses
    const int grp = lane >> 3, r8 = lane & 7;
    const uint32_t qaddr = cvta_s(sQ) + (uint32_t)(((warp*16 + ((grp&1)<<3) + r8) * QS + ((grp&2)<<2)) * 2);
    const uint32_t kaddr = cvta_s(sK) + (uint32_t)(((((grp&2)<<2) + r8) * KS + ((grp&1)<<3)) * 2);
    const uint32_t vaddr = cvta_s(sV) + (uint32_t)(((((grp&1)<<3) + r8) * VS + ((grp&2)<<2)) * 2);

    for (int kt = 0; kt < nkt; kt++) {
        __syncthreads();  // prior PV ldmatrix of sK/sV done
        // ---- Load K,V tile via paged gather -> fp16 smem ----
        {
            int row = tid >> 2;
            int qtr = tid & 3;
            int s = kt * BN + row;
            int blk = bt[b * BPS + (s >> 8)];
            size_t slot = (size_t)blk * BLKSZ + (s & 255);
            const float4* ksrc = (const float4*)(g_kc + (slot * HKV + kvh) * HDIM + qtr * 32);
            const float4* vsrc = (const float4*)(g_vc + (slot * HKV + kvh) * HDIM + qtr * 32);
            uint4* kdst = (uint4*)(sK + row * KS + qtr * 32);
            uint4* vdst = (uint4*)(sV + row * VS + qtr * 32);
            #pragma unroll
            for (int j = 0; j < 2; j++) {
                float4 a0 = ksrc[4*j], a1 = ksrc[4*j+1], a2 = ksrc[4*j+2], a3 = ksrc[4*j+3];
                uint4 t4;
                t4.x = packh2(a0.x,a0.y); t4.y = packh2(a0.z,a0.w);
                t4.z = packh2(a1.x,a1.y); t4.w = packh2(a1.z,a1.w);
                kdst[2*j] = t4;
                t4.x = packh2(a2.x,a2.y); t4.y = packh2(a2.z,a2.w);
                t4.z = packh2(a3.x,a3.y); t4.w = packh2(a3.z,a3.w);
                kdst[2*j+1] = t4;
                float4 b0 = vsrc[4*j], b1 = vsrc[4*j+1], b2 = vsrc[4*j+2], b3 = vsrc[4*j+3];
                t4.x = packh2(b0.x,b0.y); t4.y = packh2(b0.z,b0.w);
                t4.z = packh2(b1.x,b1.y); t4.w = packh2(b1.z,b1.w);
                vdst[2*j] = t4;
                t4.x = packh2(b2.x,b2.y); t4.y = packh2(b2.z,b2.w);
                t4.z = packh2(b3.x,b3.y); t4.w = packh2(b3.z,b3.w);
                vdst[2*j+1] = t4;
            }
        }
        __syncthreads();

        // ---- S = Q K^T ----
        float sacc[8][4];
        #pragma unroll
        for (int nt = 0; nt < 8; nt++) { sacc[nt][0]=sacc[nt][1]=sacc[nt][2]=sacc[nt][3]=0.f; }
        #pragma unroll
        for (int ks = 0; ks < 8; ks++) {
            uint32_t a0,a1,a2,a3;
            ldsm4(a0,a1,a2,a3, qaddr + ks*32);
            #pragma unroll
            for (int j = 0; j < 4; j++) {
                uint32_t b0,b1,b2,b3;
                ldsm4(b0,b1,b2,b3, kaddr + j*(16*KS*2) + ks*32);
                mma16816(sacc[2*j],   a0,a1,a2,a3, b0,b1);
                mma16816(sacc[2*j+1], a0,a1,a2,a3, b2,b3);
            }
        }

        // ---- Causal mask ----
        if (kt >= 2 * qi) {
            #pragma unroll
            for (int nt = 0; nt < 8; nt++) {
                int colg = kt * BN + nt * 8 + 2 * tig;
                if (colg     > rowg0) sacc[nt][0] = -1e30f;
                if (colg + 1 > rowg0) sacc[nt][1] = -1e30f;
                if (colg     > rowg1) sacc[nt][2] = -1e30f;
                if (colg + 1 > rowg1) sacc[nt][3] = -1e30f;
            }
        }

        // ---- Online softmax ----
        float mx0 = -1e30f, mx1 = -1e30f;
        #pragma unroll
        for (int nt = 0; nt < 8; nt++) {
            mx0 = fmaxf(mx0, fmaxf(sacc[nt][0], sacc[nt][1]));
            mx1 = fmaxf(mx1, fmaxf(sacc[nt][2], sacc[nt][3]));
        }
        mx0 = fmaxf(mx0, __shfl_xor_sync(0xffffffffu, mx0, 1));
        mx0 = fmaxf(mx0, __shfl_xor_sync(0xffffffffu, mx0, 2));
        mx1 = fmaxf(mx1, __shfl_xor_sync(0xffffffffu, mx1, 1));
        mx1 = fmaxf(mx1, __shfl_xor_sync(0xffffffffu, mx1, 2));
        float mn0 = fmaxf(m0, mx0);
        float mn1 = fmaxf(m1, mx1);
        float r0 = ex2f((m0 - mn0) * kf);
        float r1 = ex2f((m1 - mn1) * kf);
        m0 = mn0; m1 = mn1;
        l0 *= r0;  l1 *= r1;
        #pragma unroll
        for (int nt = 0; nt < 16; nt++) {
            o[nt][0] *= r0; o[nt][1] *= r0; o[nt][2] *= r1; o[nt][3] *= r1;
        }

        // ---- exp -> P packed in registers (A-fragment layout), row sums ----
        uint32_t pf[16];
        float rs0 = 0.f, rs1 = 0.f;
        #pragma unroll
        for (int nt = 0; nt < 8; nt++) {
            float p0 = ex2f((sacc[nt][0] - m0) * kf);
            float p1 = ex2f((sacc[nt][1] - m0) * kf);
            float p2 = ex2f((sacc[nt][2] - m1) * kf);
            float p3 = ex2f((sacc[nt][3] - m1) * kf);
            rs0 += p0 + p1;  rs1 += p2 + p3;
            pf[2*nt]   = packh2(p0, p1);
            pf[2*nt+1] = packh2(p2, p3);
        }
        rs0 += __shfl_xor_sync(0xffffffffu, rs0, 1);
        rs0 += __shfl_xor_sync(0xffffffffu, rs0, 2);
        rs1 += __shfl_xor_sync(0xffffffffu, rs1, 1);
        rs1 += __shfl_xor_sync(0xffffffffu, rs1, 2);
        l0 += rs0;  l1 += rs1;

        // ---- O += P V  (P from registers, V via ldmatrix.trans) ----
        #pragma unroll
        for (int ks = 0; ks < 4; ks++) {
            #pragma unroll
            for (int j = 0; j < 8; j++) {
                uint32_t b0,b1,b2,b3;
                ldsm4t(b0,b1,b2,b3, vaddr + ks*(16*VS*2) + j*32);
                mma16816(o[2*j],   pf[4*ks], pf[4*ks+1], pf[4*ks+2], pf[4*ks+3], b0,b1);
                mma16816(o[2*j+1], pf[4*ks], pf[4*ks+1], pf[4*ks+2], pf[4*ks+3], b2,b3);
            }
        }
    }

    // ---- Epilogue ----
    float inv0 = 1.f / l0;
    float inv1 = 1.f / l1;
    float* out0 = out + (((size_t)b * SEQ + rowg0) * NHEAD + h) * HDIM;
    float* out1 = out + (((size_t)b * SEQ + rowg1) * NHEAD + h) * HDIM;
    #pragma unroll
    for (int nt = 0; nt < 16; nt++) {
        float2 v0 = make_float2(o[nt][0] * inv0, o[nt][1] * inv0);
        float2 v1 = make_float2(o[nt][2] * inv1, o[nt][3] * inv1);
        *(float2*)(out0 + nt * 8 + 2 * tig) = v0;
        *(float2*)(out1 + nt * 8 + 2 * tig) = v1;
    }
}

extern "C" void kernel_launch(void* const* d_in, const int* in_sizes, int n_in,
                              void* d_out, int out_size) {
    (void)in_sizes; (void)n_in; (void)out_size;
    const float* q  = (const float*)d_in[0];
    const float* k  = (const float*)d_in[1];
    const float* v  = (const float*)d_in[2];
    const int* slot_mapping = (const int*)d_in[5];
    const int* block_tables = (const int*)d_in[6];
    float* out = (float*)d_out;

    cudaFuncSetAttribute(attn_kernel, cudaFuncAttributeMaxDynamicSharedMemorySize, SMEM_BYTES);

    int n4 = T_TOK * 128;
    scatter_kv<<<(n4 + 255) / 256, 256>>>(k, v, slot_mapping);

    dim3 grid(SEQ / BM, NHEAD, BATCH);
    attn_kernel<<<grid, 256, SMEM_BYTES>>>(q, block_tables, out);
}